// round 6
// baseline (speedup 1.0000x reference)
#include <cuda_runtime.h>
#include <math.h>

#define B_ 256
#define T_ 256
#define F_ 128
#define H_ 512
#define BT (B_*T_)

// ---------------- scratch (static __device__ allocations; no cudaMalloc) ----
__device__ float g_xm[(size_t)BT * 256];        // [BT][256] = x_rep | m
__device__ float g_gamma_h[(size_t)BT * H_];    // [BT][512]
__device__ float g_gi[(size_t)BT * 1536];       // [BT][1536] gi_pre (x/m part + b_ih)
__device__ float g_Wpack[6 * H_ * H_];          // [6][512][512]
__device__ float g_W2[1536 * 256];              // [1536][256]
__device__ float g_h[2][B_ * H_];               // ping-pong hidden state

// ---------------- f32x2 helpers --------------------------------------------
#define FMA2(d, a, b) asm("fma.rn.f32x2 %0, %1, %2, %0;" : "+l"(d) : "l"(a), "l"(b))
#define UNPK2(lo, hi, v) asm("mov.b64 {%0, %1}, %2;" : "=f"(lo), "=f"(hi) : "l"(v))
#define DUP2(d, v) asm("mov.b64 %0, {%1, %1};" : "=l"(d) : "f"(v))

// ---------------- pack kernels ---------------------------------------------
__global__ void __launch_bounds__(256) pack_w2_kernel(const float* __restrict__ W_ih) {
    int idx = blockIdx.x * 256 + threadIdx.x;       // 1536*256
    int row = idx >> 8, k = idx & 255;
    // A rows are [x_rep(128) | m(128)]; W_ih cols: [x(0:128) | h(128:640) | m(640:768)]
    float v = (k < 128) ? W_ih[row * 768 + k] : W_ih[row * 768 + 512 + k];
    g_W2[idx] = v;
}

__global__ void __launch_bounds__(256) pack_wp_kernel(const float* __restrict__ W_ih,
                                                      const float* __restrict__ W_hh) {
    int idx = blockIdx.x * 256 + threadIdx.x;       // 6*512*512
    int k = idx & 511;
    int j = (idx >> 9) & 511;
    int g = idx >> 18;
    float v = (g < 3) ? W_ih[(g * 512 + j) * 768 + 128 + k]
                      : W_hh[((g - 3) * 512 + j) * 512 + k];
    g_Wpack[idx] = v;
}

__global__ void __launch_bounds__(256) zero_h_kernel() {
    g_h[0][blockIdx.x * 256 + threadIdx.x] = 0.0f;
}

// ---------------- elementwise: x_rep / m packing ----------------------------
__global__ void __launch_bounds__(256) xm_kernel(const float* __restrict__ values,
                          const float* __restrict__ masks,
                          const float* __restrict__ deltas,
                          const float* __restrict__ emean,
                          const float* __restrict__ xlocf,
                          const float* __restrict__ wx,
                          const float* __restrict__ bx) {
    int idx = blockIdx.x * 256 + threadIdx.x;       // BT*F
    int f = idx & 127;
    int r = idx >> 7;
    float d = deltas[idx];
    float a = d * wx[f] + bx[f];
    float gx = (a > 0.0f) ? expf(-a) : 1.0f;
    float m = masks[idx];
    float xh = gx * xlocf[idx] + (1.0f - gx) * emean[f];
    float xr = m * values[idx] + (1.0f - m) * xh;
    g_xm[(size_t)r * 256 + f] = xr;
    g_xm[(size_t)r * 256 + 128 + f] = m;
}

// ---------------- generic precompute GEMM: C = f(A @ W^T + bias) ------------
// BM=64, BN=64, Kc=16, 256 threads, per-thread 4x4 via f32x2 pairs.
// which==0: gamma_h = exp(-relu(deltas @ Wh^T + bh))    [BT,128]x[512,128]^T
// which==1: gi_pre  = g_xm @ g_W2^T + b_ih              [BT,256]x[1536,256]^T
__global__ void __launch_bounds__(256) gemm_f2_kernel(const float* __restrict__ Ap,
                               const float* __restrict__ Wp,
                               const float* __restrict__ bias,
                               int which) {
    const float* __restrict__ A;
    const float* __restrict__ W;
    float* __restrict__ C;
    int N, K;
    if (which == 0) { A = Ap;   W = Wp;   C = g_gamma_h; N = 512;  K = 128; }
    else            { A = g_xm; W = g_W2; C = g_gi;      N = 1536; K = 256; }

    __shared__ __align__(16) float As[16 * 130];    // [k][2*row] duplicated, stride 130
    __shared__ __align__(16) float Bs[16 * 66];     // [k][col], stride 66
    const int tid = threadIdx.x;
    const int m0 = blockIdx.y * 64;
    const int n0 = blockIdx.x * 64;
    const int lr = tid >> 2;            // 0..63 tile row for loads
    const int kq = (tid & 3) << 2;      // k sub-offset (0,4,8,12)
    const int ty = tid >> 4, tx = tid & 15;

    unsigned long long acc[4][2];
#pragma unroll
    for (int r = 0; r < 4; r++) { acc[r][0] = 0ull; acc[r][1] = 0ull; }

    for (int k0 = 0; k0 < K; k0 += 16) {
        float4 av = *(const float4*)(A + (size_t)(m0 + lr) * K + k0 + kq);
        float4 bv = *(const float4*)(W + (size_t)(n0 + lr) * K + k0 + kq);
        __syncthreads();
        As[(kq + 0) * 130 + 2 * lr] = av.x; As[(kq + 0) * 130 + 2 * lr + 1] = av.x;
        As[(kq + 1) * 130 + 2 * lr] = av.y; As[(kq + 1) * 130 + 2 * lr + 1] = av.y;
        As[(kq + 2) * 130 + 2 * lr] = av.z; As[(kq + 2) * 130 + 2 * lr + 1] = av.z;
        As[(kq + 3) * 130 + 2 * lr] = av.w; As[(kq + 3) * 130 + 2 * lr + 1] = av.w;
        Bs[(kq + 0) * 66 + lr] = bv.x;
        Bs[(kq + 1) * 66 + lr] = bv.y;
        Bs[(kq + 2) * 66 + lr] = bv.z;
        Bs[(kq + 3) * 66 + lr] = bv.w;
        __syncthreads();
#pragma unroll
        for (int kk = 0; kk < 16; kk++) {
            unsigned long long b01 = *(const unsigned long long*)&Bs[kk * 66 + tx * 4];
            unsigned long long b23 = *(const unsigned long long*)&Bs[kk * 66 + tx * 4 + 2];
#pragma unroll
            for (int r = 0; r < 4; r++) {
                unsigned long long ad =
                    *(const unsigned long long*)&As[kk * 130 + (ty * 4 + r) * 2];
                FMA2(acc[r][0], ad, b01);
                FMA2(acc[r][1], ad, b23);
            }
        }
    }
    const int n = n0 + tx * 4;
    float b0v = bias[n], b1v = bias[n + 1], b2v = bias[n + 2], b3v = bias[n + 3];
#pragma unroll
    for (int r = 0; r < 4; r++) {
        int m = m0 + ty * 4 + r;
        float4 v;
        UNPK2(v.x, v.y, acc[r][0]);
        UNPK2(v.z, v.w, acc[r][1]);
        v.x += b0v; v.y += b1v; v.z += b2v; v.w += b3v;
        if (which == 0) {
            v.x = (v.x > 0.0f) ? expf(-v.x) : 1.0f;
            v.y = (v.y > 0.0f) ? expf(-v.y) : 1.0f;
            v.z = (v.z > 0.0f) ? expf(-v.z) : 1.0f;
            v.w = (v.w > 0.0f) ? expf(-v.w) : 1.0f;
        }
        *(float4*)(C + (size_t)m * N + n) = v;
    }
}

// ---------------- fused per-timestep kernel ---------------------------------
// Block: 32 batch rows x 32 h-cols x 6 gates (192 GEMM cols), K = 512.
// 512 threads = 4 row-groups (8 rows/warp) x 4 k-groups (8 kk/slab each).
// Grid: (H/32=16, B/32=8) = 128 blocks.
// Partial-sum reduction over k-groups: 4 staged dump rounds reusing Ws.
__global__ void __launch_bounds__(512) step_kernel(int t, const float* __restrict__ b_hh,
                            float* __restrict__ out) {
    __shared__ __align__(16) float Ws[32 * 194];    // [k][c] stride 194 (also S buffer)
    __shared__ __align__(16) float Ad[32 * 66];     // [k][2*row] duplicated
    const int tid = threadIdx.x;
    const int h0 = blockIdx.x * 32;
    const int b0 = blockIdx.y * 32;
    const float* __restrict__ hin = g_h[t & 1];
    float* __restrict__ hout = g_h[(t + 1) & 1];

    const int lid = tid & 31;
    const int wid = tid >> 5;
    const int kg  = wid & 3;          // k-group 0..3 (kk = kg*8 .. +8 per slab)
    const int rgp = wid >> 2;         // row-group 0..3 (rows rgp*8 .. +8)

    // h/gamma load mapping: 32 rows x 16 float2 (coalesced)
    const int hr = tid >> 4;          // row 0..31
    const int hk = (tid & 15) << 1;   // k offset (even)

    unsigned long long acc[8][3];
#pragma unroll
    for (int rr = 0; rr < 8; rr++) {
        acc[rr][0] = 0ull; acc[rr][1] = 0ull; acc[rr][2] = 0ull;
    }

    for (int k0 = 0; k0 < 512; k0 += 32) {
        float2 hv = *(const float2*)(hin + (b0 + hr) * H_ + k0 + hk);
        float2 gv = *(const float2*)(g_gamma_h +
                       ((size_t)(b0 + hr) * T_ + t) * H_ + k0 + hk);
        // W: 192 cols x 32 k = 1536 float4, 3 per thread
        float4 wv[3];
        int wc[3], wk[3];
#pragma unroll
        for (int i = 0; i < 3; i++) {
            int f = i * 512 + tid;
            wc[i] = f >> 3;                 // col 0..191
            wk[i] = (f & 7) << 2;           // k quarter
            int g = wc[i] >> 5, jh = wc[i] & 31;
            wv[i] = *(const float4*)(g_Wpack +
                        ((size_t)g * H_ + h0 + jh) * 512 + k0 + wk[i]);
        }
        __syncthreads();
        {
            float a0 = hv.x * gv.x, a1 = hv.y * gv.y;
            unsigned long long p0, p1;
            DUP2(p0, a0);
            DUP2(p1, a1);
            *(unsigned long long*)&Ad[(hk + 0) * 66 + 2 * hr] = p0;
            *(unsigned long long*)&Ad[(hk + 1) * 66 + 2 * hr] = p1;
        }
#pragma unroll
        for (int i = 0; i < 3; i++) {
            Ws[(wk[i] + 0) * 194 + wc[i]] = wv[i].x;
            Ws[(wk[i] + 1) * 194 + wc[i]] = wv[i].y;
            Ws[(wk[i] + 2) * 194 + wc[i]] = wv[i].z;
            Ws[(wk[i] + 3) * 194 + wc[i]] = wv[i].w;
        }
        __syncthreads();
#pragma unroll
        for (int kx = 0; kx < 8; kx++) {
            const int kk = kg * 8 + kx;
            unsigned long long bp0 = *(const unsigned long long*)&Ws[kk * 194 + 2 * lid];
            unsigned long long bp1 = *(const unsigned long long*)&Ws[kk * 194 + 2 * lid + 64];
            unsigned long long bp2 = *(const unsigned long long*)&Ws[kk * 194 + 2 * lid + 128];
#pragma unroll
            for (int rr = 0; rr < 8; rr++) {
                unsigned long long ad =
                    *(const unsigned long long*)&Ad[kk * 66 + (rgp * 8 + rr) * 2];
                FMA2(acc[rr][0], ad, bp0);
                FMA2(acc[rr][1], ad, bp1);
                FMA2(acc[rr][2], ad, bp2);
            }
        }
    }

    // staged k-group reduction: 4 rounds, each reuses Ws as S[row][c] (stride 194)
    float u[2][6];
#pragma unroll
    for (int it = 0; it < 2; it++)
#pragma unroll
        for (int g = 0; g < 6; g++) u[it][g] = 0.0f;

    for (int round = 0; round < 4; round++) {
        __syncthreads();
        if (kg == round) {
#pragma unroll
            for (int rr = 0; rr < 8; rr++) {
#pragma unroll
                for (int j = 0; j < 3; j++) {
                    *(unsigned long long*)&Ws[(rgp * 8 + rr) * 194 + 2 * lid + 64 * j] =
                        acc[rr][j];
                }
            }
        }
        __syncthreads();
#pragma unroll
        for (int it = 0; it < 2; it++) {
            int item = it * 512 + tid;
            int row = item >> 5, jh = item & 31;
#pragma unroll
            for (int g = 0; g < 6; g++)
                u[it][g] += Ws[row * 194 + g * 32 + jh];
        }
    }

    // gate nonlinearity + state update: 32x32 items, 2 per thread
#pragma unroll
    for (int it = 0; it < 2; it++) {
        int item = it * 512 + tid;
        int row = item >> 5, jh = item & 31;
        int gb = b0 + row, gj = h0 + jh;
        size_t ridx = (size_t)gb * T_ + t;
        const float* gi = g_gi + ridx * 1536 + gj;
        float ir  = gi[0]    + u[it][0];
        float iz  = gi[512]  + u[it][1];
        float in_ = gi[1024] + u[it][2];
        float hr_ = u[it][3] + b_hh[gj];
        float hz  = u[it][4] + b_hh[512 + gj];
        float hn  = u[it][5] + b_hh[1024 + gj];
        float hd = hin[gb * H_ + gj] * g_gamma_h[ridx * H_ + gj];
        float r = 1.0f / (1.0f + expf(-(ir + hr_)));
        float z = 1.0f / (1.0f + expf(-(iz + hz)));
        float n = tanhf(in_ + r * hn);
        float hvn = (1.0f - z) * n + z * hd;
        hout[gb * H_ + gj] = hvn;
        out[ridx * H_ + gj] = hvn;
        if (t == T_ - 1) out[(size_t)BT * H_ + (size_t)gb * H_ + gj] = hvn;
    }
}

// ---------------- launch ----------------------------------------------------
// Pure kernel launches only.
extern "C" void kernel_launch(void* const* d_in, const int* in_sizes, int n_in,
                              void* d_out, int out_size) {
    const float* values = (const float*)d_in[0];
    const float* masks  = (const float*)d_in[1];
    const float* deltas = (const float*)d_in[2];
    const float* emean  = (const float*)d_in[3];
    const float* xlocf  = (const float*)d_in[4];
    const float* wx     = (const float*)d_in[5];
    const float* bx     = (const float*)d_in[6];
    const float* Wh     = (const float*)d_in[7];
    const float* bh     = (const float*)d_in[8];
    const float* W_ih   = (const float*)d_in[9];
    const float* W_hh   = (const float*)d_in[10];
    const float* b_ih   = (const float*)d_in[11];
    const float* b_hh   = (const float*)d_in[12];
    float* out = (float*)d_out;

    pack_w2_kernel<<<(1536 * 256) / 256, 256>>>(W_ih);
    pack_wp_kernel<<<(6 * 512 * 512) / 256, 256>>>(W_ih, W_hh);
    xm_kernel<<<(BT * F_) / 256, 256>>>(values, masks, deltas, emean, xlocf, wx, bx);
    zero_h_kernel<<<(B_ * H_) / 256, 256>>>();
    // gamma_h = exp(-relu(deltas @ Wh^T + bh)) : [BT,128] x [512,128]^T
    gemm_f2_kernel<<<dim3(512 / 64, BT / 64), 256>>>(deltas, Wh, bh, 0);
    // gi_pre = xm @ W2^T + b_ih : [BT,256] x [1536,256]^T (A/W resolved in-kernel)
    gemm_f2_kernel<<<dim3(1536 / 64, BT / 64), 256>>>(nullptr, nullptr, b_ih, 1);
    for (int t = 0; t < T_; t++)
        step_kernel<<<dim3(16, 8), 512>>>(t, b_hh, out);
}

// round 7
// speedup vs baseline: 1.5020x; 1.5020x over previous
#include <cuda_runtime.h>
#include <math.h>

#define B_ 256
#define T_ 256
#define F_ 128
#define H_ 512
#define BT (B_*T_)
#define NCTA 128

// ---------------- scratch (static __device__ allocations; no cudaMalloc) ----
__device__ float g_xm[(size_t)BT * 256];        // [BT][256] = x_rep | m
__device__ float g_gamma_h[(size_t)BT * H_];    // [BT][512]
__device__ float g_gi[(size_t)BT * 1536];       // [BT][1536] gi_pre (x/m part + b_ih)
__device__ float g_Wpack[6 * H_ * H_];          // [6][512][512]
__device__ float g_W2[1536 * 256];              // [1536][256]
__device__ float g_h[2][B_ * H_];               // ping-pong hidden state
__device__ unsigned int g_bar_arrive;           // grid-barrier arrive counter
__device__ unsigned int g_bar_gen;              // grid-barrier generation

// ---------------- f32x2 helpers --------------------------------------------
#define FMA2(d, a, b) asm("fma.rn.f32x2 %0, %1, %2, %0;" : "+l"(d) : "l"(a), "l"(b))
#define UNPK2(lo, hi, v) asm("mov.b64 {%0, %1}, %2;" : "=f"(lo), "=f"(hi) : "l"(v))
#define DUP2(d, v) asm("mov.b64 %0, {%1, %1};" : "=l"(d) : "f"(v))

// ---------------- pack kernels ---------------------------------------------
__global__ void __launch_bounds__(256) pack_w2_kernel(const float* __restrict__ W_ih) {
    int idx = blockIdx.x * 256 + threadIdx.x;       // 1536*256
    int row = idx >> 8, k = idx & 255;
    // A rows are [x_rep(128) | m(128)]; W_ih cols: [x(0:128) | h(128:640) | m(640:768)]
    float v = (k < 128) ? W_ih[row * 768 + k] : W_ih[row * 768 + 512 + k];
    g_W2[idx] = v;
}

__global__ void __launch_bounds__(256) pack_wp_kernel(const float* __restrict__ W_ih,
                                                      const float* __restrict__ W_hh) {
    int idx = blockIdx.x * 256 + threadIdx.x;       // 6*512*512
    int k = idx & 511;
    int j = (idx >> 9) & 511;
    int g = idx >> 18;
    float v = (g < 3) ? W_ih[(g * 512 + j) * 768 + 128 + k]
                      : W_hh[((g - 3) * 512 + j) * 512 + k];
    g_Wpack[idx] = v;
}

__global__ void __launch_bounds__(256) zero_h_kernel() {
    g_h[0][blockIdx.x * 256 + threadIdx.x] = 0.0f;
    if (blockIdx.x == 0 && threadIdx.x == 0) {
        g_bar_arrive = 0u;
        g_bar_gen = 0u;
    }
}

// ---------------- elementwise: x_rep / m packing ----------------------------
__global__ void __launch_bounds__(256) xm_kernel(const float* __restrict__ values,
                          const float* __restrict__ masks,
                          const float* __restrict__ deltas,
                          const float* __restrict__ emean,
                          const float* __restrict__ xlocf,
                          const float* __restrict__ wx,
                          const float* __restrict__ bx) {
    int idx = blockIdx.x * 256 + threadIdx.x;       // BT*F
    int f = idx & 127;
    int r = idx >> 7;
    float d = deltas[idx];
    float a = d * wx[f] + bx[f];
    float gx = (a > 0.0f) ? expf(-a) : 1.0f;
    float m = masks[idx];
    float xh = gx * xlocf[idx] + (1.0f - gx) * emean[f];
    float xr = m * values[idx] + (1.0f - m) * xh;
    g_xm[(size_t)r * 256 + f] = xr;
    g_xm[(size_t)r * 256 + 128 + f] = m;
}

// ---------------- generic precompute GEMM: C = f(A @ W^T + bias) ------------
// BM=64, BN=64, Kc=16, 256 threads, per-thread 4x4 via f32x2 pairs.
// which==0: gamma_h = exp(-relu(deltas @ Wh^T + bh))    [BT,128]x[512,128]^T
// which==1: gi_pre  = g_xm @ g_W2^T + b_ih              [BT,256]x[1536,256]^T
__global__ void __launch_bounds__(256) gemm_f2_kernel(const float* __restrict__ Ap,
                               const float* __restrict__ Wp,
                               const float* __restrict__ bias,
                               int which) {
    const float* __restrict__ A;
    const float* __restrict__ W;
    float* __restrict__ C;
    int N, K;
    if (which == 0) { A = Ap;   W = Wp;   C = g_gamma_h; N = 512;  K = 128; }
    else            { A = g_xm; W = g_W2; C = g_gi;      N = 1536; K = 256; }

    __shared__ __align__(16) float As[16 * 130];    // [k][2*row] duplicated, stride 130
    __shared__ __align__(16) float Bs[16 * 66];     // [k][col], stride 66
    const int tid = threadIdx.x;
    const int m0 = blockIdx.y * 64;
    const int n0 = blockIdx.x * 64;
    const int lr = tid >> 2;            // 0..63 tile row for loads
    const int kq = (tid & 3) << 2;      // k sub-offset (0,4,8,12)
    const int ty = tid >> 4, tx = tid & 15;

    unsigned long long acc[4][2];
#pragma unroll
    for (int r = 0; r < 4; r++) { acc[r][0] = 0ull; acc[r][1] = 0ull; }

    for (int k0 = 0; k0 < K; k0 += 16) {
        float4 av = *(const float4*)(A + (size_t)(m0 + lr) * K + k0 + kq);
        float4 bv = *(const float4*)(W + (size_t)(n0 + lr) * K + k0 + kq);
        __syncthreads();
        As[(kq + 0) * 130 + 2 * lr] = av.x; As[(kq + 0) * 130 + 2 * lr + 1] = av.x;
        As[(kq + 1) * 130 + 2 * lr] = av.y; As[(kq + 1) * 130 + 2 * lr + 1] = av.y;
        As[(kq + 2) * 130 + 2 * lr] = av.z; As[(kq + 2) * 130 + 2 * lr + 1] = av.z;
        As[(kq + 3) * 130 + 2 * lr] = av.w; As[(kq + 3) * 130 + 2 * lr + 1] = av.w;
        Bs[(kq + 0) * 66 + lr] = bv.x;
        Bs[(kq + 1) * 66 + lr] = bv.y;
        Bs[(kq + 2) * 66 + lr] = bv.z;
        Bs[(kq + 3) * 66 + lr] = bv.w;
        __syncthreads();
#pragma unroll
        for (int kk = 0; kk < 16; kk++) {
            unsigned long long b01 = *(const unsigned long long*)&Bs[kk * 66 + tx * 4];
            unsigned long long b23 = *(const unsigned long long*)&Bs[kk * 66 + tx * 4 + 2];
#pragma unroll
            for (int r = 0; r < 4; r++) {
                unsigned long long ad =
                    *(const unsigned long long*)&As[kk * 130 + (ty * 4 + r) * 2];
                FMA2(acc[r][0], ad, b01);
                FMA2(acc[r][1], ad, b23);
            }
        }
    }
    const int n = n0 + tx * 4;
    float b0v = bias[n], b1v = bias[n + 1], b2v = bias[n + 2], b3v = bias[n + 3];
#pragma unroll
    for (int r = 0; r < 4; r++) {
        int m = m0 + ty * 4 + r;
        float4 v;
        UNPK2(v.x, v.y, acc[r][0]);
        UNPK2(v.z, v.w, acc[r][1]);
        v.x += b0v; v.y += b1v; v.z += b2v; v.w += b3v;
        if (which == 0) {
            v.x = (v.x > 0.0f) ? expf(-v.x) : 1.0f;
            v.y = (v.y > 0.0f) ? expf(-v.y) : 1.0f;
            v.z = (v.z > 0.0f) ? expf(-v.z) : 1.0f;
            v.w = (v.w > 0.0f) ? expf(-v.w) : 1.0f;
        }
        *(float4*)(C + (size_t)m * N + n) = v;
    }
}

// ---------------- persistent scan kernel ------------------------------------
// One launch covers all T=256 timesteps; software grid barrier between steps.
// Block: 32 batch rows x 32 h-cols x 6 gates (192 GEMM cols), K = 512.
// 256 threads = 8 warps = 4 row-groups (8 rows each) x 2 k-groups (16 kk each).
// Grid: (H/32=16, B/32=8) = 128 CTAs <= 148 SMs -> all co-resident (barrier safe).
__global__ void __launch_bounds__(256) scan_kernel(const float* __restrict__ b_hh,
                                                   float* __restrict__ out) {
    __shared__ __align__(16) float Ws[32 * 194];    // [k][c] stride 194 (also S buffer)
    __shared__ __align__(16) float Ad[32 * 66];     // [k][2*row] duplicated
    const int tid = threadIdx.x;
    const int h0 = blockIdx.x * 32;
    const int b0 = blockIdx.y * 32;

    const int lid = tid & 31;
    const int wid = tid >> 5;
    const int kg  = wid & 1;          // k-group 0..1 (kk = kg*16 .. +16 per slab)
    const int rgp = wid >> 1;         // row-group 0..3 (rows rgp*8 .. +8)

    const int ar = tid >> 3;          // h-load row 0..31
    const int akq = (tid & 7) << 2;   // h-load k quarter

    // per-thread persistent bias registers for epilogue (4 items/thread)
    int e_row[4], e_jh[4];
#pragma unroll
    for (int it = 0; it < 4; it++) {
        int item = it * 256 + tid;
        e_row[it] = item >> 5;
        e_jh[it]  = item & 31;
    }

    for (int t = 0; t < T_; t++) {
        const float* __restrict__ hin = g_h[t & 1];
        float* __restrict__ hout = g_h[(t + 1) & 1];

        unsigned long long acc[8][3];
#pragma unroll
        for (int rr = 0; rr < 8; rr++) {
            acc[rr][0] = 0ull; acc[rr][1] = 0ull; acc[rr][2] = 0ull;
        }

        for (int k0 = 0; k0 < 512; k0 += 32) {
            float4 hv = *(const float4*)(hin + (b0 + ar) * H_ + k0 + akq);
            float4 gv = *(const float4*)(g_gamma_h +
                           ((size_t)(b0 + ar) * T_ + t) * H_ + k0 + akq);
            // W: 192 cols x 32 k = 1536 float4, 6 per thread
            float4 wv[6];
            int wc[6], wk[6];
#pragma unroll
            for (int i = 0; i < 6; i++) {
                int f = i * 256 + tid;
                wc[i] = f >> 3;                 // col 0..191
                wk[i] = (f & 7) << 2;           // k quarter
                int g = wc[i] >> 5, jh = wc[i] & 31;
                wv[i] = *(const float4*)(g_Wpack +
                            ((size_t)g * H_ + h0 + jh) * 512 + k0 + wk[i]);
            }
            __syncthreads();
            {
                float a0 = hv.x * gv.x, a1 = hv.y * gv.y;
                float a2 = hv.z * gv.z, a3 = hv.w * gv.w;
                unsigned long long p0, p1, p2, p3;
                DUP2(p0, a0); DUP2(p1, a1); DUP2(p2, a2); DUP2(p3, a3);
                *(unsigned long long*)&Ad[(akq + 0) * 66 + 2 * ar] = p0;
                *(unsigned long long*)&Ad[(akq + 1) * 66 + 2 * ar] = p1;
                *(unsigned long long*)&Ad[(akq + 2) * 66 + 2 * ar] = p2;
                *(unsigned long long*)&Ad[(akq + 3) * 66 + 2 * ar] = p3;
            }
#pragma unroll
            for (int i = 0; i < 6; i++) {
                Ws[(wk[i] + 0) * 194 + wc[i]] = wv[i].x;
                Ws[(wk[i] + 1) * 194 + wc[i]] = wv[i].y;
                Ws[(wk[i] + 2) * 194 + wc[i]] = wv[i].z;
                Ws[(wk[i] + 3) * 194 + wc[i]] = wv[i].w;
            }
            __syncthreads();
#pragma unroll
            for (int kx = 0; kx < 16; kx++) {
                const int kk = kg * 16 + kx;
                unsigned long long bp0 = *(const unsigned long long*)&Ws[kk * 194 + 2 * lid];
                unsigned long long bp1 = *(const unsigned long long*)&Ws[kk * 194 + 2 * lid + 64];
                unsigned long long bp2 = *(const unsigned long long*)&Ws[kk * 194 + 2 * lid + 128];
#pragma unroll
                for (int rr = 0; rr < 8; rr++) {
                    unsigned long long ad =
                        *(const unsigned long long*)&Ad[kk * 66 + (rgp * 8 + rr) * 2];
                    FMA2(acc[rr][0], ad, bp0);
                    FMA2(acc[rr][1], ad, bp1);
                    FMA2(acc[rr][2], ad, bp2);
                }
            }
        }

        // staged k-group reduction: 2 rounds, reusing Ws as S[row][c] (stride 194)
        float u[4][6];
#pragma unroll
        for (int it = 0; it < 4; it++)
#pragma unroll
            for (int g = 0; g < 6; g++) u[it][g] = 0.0f;

        for (int round = 0; round < 2; round++) {
            __syncthreads();
            if (kg == round) {
#pragma unroll
                for (int rr = 0; rr < 8; rr++) {
#pragma unroll
                    for (int j = 0; j < 3; j++) {
                        *(unsigned long long*)&Ws[(rgp * 8 + rr) * 194 + 2 * lid + 64 * j] =
                            acc[rr][j];
                    }
                }
            }
            __syncthreads();
#pragma unroll
            for (int it = 0; it < 4; it++) {
#pragma unroll
                for (int g = 0; g < 6; g++)
                    u[it][g] += Ws[e_row[it] * 194 + g * 32 + e_jh[it]];
            }
        }

        // gate nonlinearity + state update: 32x32 items, 4 per thread
#pragma unroll
        for (int it = 0; it < 4; it++) {
            int gb = b0 + e_row[it], gj = h0 + e_jh[it];
            size_t ridx = (size_t)gb * T_ + t;
            const float* gi = g_gi + ridx * 1536 + gj;
            float ir  = gi[0]    + u[it][0];
            float iz  = gi[512]  + u[it][1];
            float in_ = gi[1024] + u[it][2];
            float hr_ = u[it][3] + b_hh[gj];
            float hz  = u[it][4] + b_hh[512 + gj];
            float hn  = u[it][5] + b_hh[1024 + gj];
            float hd = hin[gb * H_ + gj] * g_gamma_h[ridx * H_ + gj];
            float r = 1.0f / (1.0f + expf(-(ir + hr_)));
            float z = 1.0f / (1.0f + expf(-(iz + hz)));
            float n = tanhf(in_ + r * hn);
            float hvn = (1.0f - z) * n + z * hd;
            hout[gb * H_ + gj] = hvn;
            out[ridx * H_ + gj] = hvn;
            if (t == T_ - 1) out[(size_t)BT * H_ + (size_t)gb * H_ + gj] = hvn;
        }

        // ---- software grid barrier (all 128 CTAs co-resident) ----
        if (t < T_ - 1) {
            __syncthreads();
            if (tid == 0) {
                __threadfence();
                unsigned int ticket = atomicAdd(&g_bar_arrive, 1u);
                if (ticket == NCTA - 1) {
                    g_bar_arrive = 0u;
                    __threadfence();
                    atomicExch(&g_bar_gen, (unsigned int)(t + 1));
                } else {
                    while (atomicAdd(&g_bar_gen, 0u) < (unsigned int)(t + 1)) { }
                }
            }
            __syncthreads();
        }
    }
}

// ---------------- launch ----------------------------------------------------
// Pure kernel launches only; 7 graph nodes total.
extern "C" void kernel_launch(void* const* d_in, const int* in_sizes, int n_in,
                              void* d_out, int out_size) {
    const float* values = (const float*)d_in[0];
    const float* masks  = (const float*)d_in[1];
    const float* deltas = (const float*)d_in[2];
    const float* emean  = (const float*)d_in[3];
    const float* xlocf  = (const float*)d_in[4];
    const float* wx     = (const float*)d_in[5];
    const float* bx     = (const float*)d_in[6];
    const float* Wh     = (const float*)d_in[7];
    const float* bh     = (const float*)d_in[8];
    const float* W_ih   = (const float*)d_in[9];
    const float* W_hh   = (const float*)d_in[10];
    const float* b_ih   = (const float*)d_in[11];
    const float* b_hh   = (const float*)d_in[12];
    float* out = (float*)d_out;

    pack_w2_kernel<<<(1536 * 256) / 256, 256>>>(W_ih);
    pack_wp_kernel<<<(6 * 512 * 512) / 256, 256>>>(W_ih, W_hh);
    xm_kernel<<<(BT * F_) / 256, 256>>>(values, masks, deltas, emean, xlocf, wx, bx);
    zero_h_kernel<<<(B_ * H_) / 256, 256>>>();
    // gamma_h = exp(-relu(deltas @ Wh^T + bh)) : [BT,128] x [512,128]^T
    gemm_f2_kernel<<<dim3(512 / 64, BT / 64), 256>>>(deltas, Wh, bh, 0);
    // gi_pre = xm @ W2^T + b_ih : [BT,256] x [1536,256]^T (A/W resolved in-kernel)
    gemm_f2_kernel<<<dim3(1536 / 64, BT / 64), 256>>>(nullptr, nullptr, b_ih, 1);
    // persistent scan over all timesteps
    scan_kernel<<<dim3(16, 8), 256>>>(b_hh, out);
}

// round 9
// speedup vs baseline: 1.5085x; 1.0043x over previous
#include <cuda_runtime.h>
#include <math.h>

#define B_ 256
#define T_ 256
#define F_ 128
#define H_ 512
#define BT (B_*T_)
#define NCTA 128

// ---------------- scratch (static __device__ allocations; no cudaMalloc) ----
__device__ float g_xm[(size_t)BT * 256];        // [BT][256] = x_rep | m
__device__ float g_gamma_h[(size_t)BT * H_];    // [BT][512]
__device__ float g_gi[(size_t)BT * 1536];       // [BT][1536] gi_pre (x/m part + b_ih)
__device__ float g_Wt[16 * 512 * 192];          // [hb][k][c=g*32+jh] transposed weights
__device__ float g_W2[1536 * 256];              // [1536][256]
__device__ float g_h[2][B_ * H_];               // ping-pong hidden state
__device__ int   g_flags[NCTA];                 // per-CTA arrival flags
__device__ int   g_gen;                         // barrier generation (release word)

// ---------------- f32x2 helpers --------------------------------------------
#define FMA2(d, a, b) asm("fma.rn.f32x2 %0, %1, %2, %0;" : "+l"(d) : "l"(a), "l"(b))
#define UNPK2(lo, hi, v) asm("mov.b64 {%0, %1}, %2;" : "=f"(lo), "=f"(hi) : "l"(v))
#define DUP2(d, v) asm("mov.b64 %0, {%1, %1};" : "=l"(d) : "f"(v))

// ---------------- pack kernels ---------------------------------------------
__global__ void __launch_bounds__(256) pack_w2_kernel(const float* __restrict__ W_ih) {
    int idx = blockIdx.x * 256 + threadIdx.x;       // 1536*256
    int row = idx >> 8, k = idx & 255;
    // A rows are [x_rep(128) | m(128)]; W_ih cols: [x(0:128) | h(128:640) | m(640:768)]
    float v = (k < 128) ? W_ih[row * 768 + k] : W_ih[row * 768 + 512 + k];
    g_W2[idx] = v;
}

// transposed pack: g_Wt[hb][k][c], c = g*32 + jh; value = W(gate g, col hb*32+jh, k)
__global__ void __launch_bounds__(256) pack_wt_kernel(const float* __restrict__ W_ih,
                                                      const float* __restrict__ W_hh) {
    int idx = blockIdx.x * 256 + threadIdx.x;       // 16*512*192 = 1,572,864
    int c = idx % 192;
    int r = idx / 192;
    int k = r & 511;
    int hb = r >> 9;
    int g = c >> 5, jh = c & 31;
    int col = hb * 32 + jh;
    float v = (g < 3) ? W_ih[(g * 512 + col) * 768 + 128 + k]
                      : W_hh[((g - 3) * 512 + col) * 512 + k];
    g_Wt[idx] = v;
}

__global__ void __launch_bounds__(256) zero_h_kernel() {
    g_h[0][blockIdx.x * 256 + threadIdx.x] = 0.0f;
    if (blockIdx.x == 0) {
        if (threadIdx.x < NCTA) g_flags[threadIdx.x] = 0;
        if (threadIdx.x == 0) g_gen = 0;
    }
}

// ---------------- elementwise: x_rep / m packing ----------------------------
__global__ void __launch_bounds__(256) xm_kernel(const float* __restrict__ values,
                          const float* __restrict__ masks,
                          const float* __restrict__ deltas,
                          const float* __restrict__ emean,
                          const float* __restrict__ xlocf,
                          const float* __restrict__ wx,
                          const float* __restrict__ bx) {
    int idx = blockIdx.x * 256 + threadIdx.x;       // BT*F
    int f = idx & 127;
    int r = idx >> 7;
    float d = deltas[idx];
    float a = d * wx[f] + bx[f];
    float gx = (a > 0.0f) ? expf(-a) : 1.0f;
    float m = masks[idx];
    float xh = gx * xlocf[idx] + (1.0f - gx) * emean[f];
    float xr = m * values[idx] + (1.0f - m) * xh;
    g_xm[(size_t)r * 256 + f] = xr;
    g_xm[(size_t)r * 256 + 128 + f] = m;
}

// ---------------- generic precompute GEMM: C = f(A @ W^T + bias) ------------
// BM=64, BN=64, Kc=16, 256 threads, per-thread 4x4 via f32x2 pairs.
__global__ void __launch_bounds__(256) gemm_f2_kernel(const float* __restrict__ Ap,
                               const float* __restrict__ Wp,
                               const float* __restrict__ bias,
                               int which) {
    const float* __restrict__ A;
    const float* __restrict__ W;
    float* __restrict__ C;
    int N, K;
    if (which == 0) { A = Ap;   W = Wp;   C = g_gamma_h; N = 512;  K = 128; }
    else            { A = g_xm; W = g_W2; C = g_gi;      N = 1536; K = 256; }

    __shared__ __align__(16) float As[16 * 130];    // [k][2*row] duplicated, stride 130
    __shared__ __align__(16) float Bs[16 * 66];     // [k][col], stride 66
    const int tid = threadIdx.x;
    const int m0 = blockIdx.y * 64;
    const int n0 = blockIdx.x * 64;
    const int lr = tid >> 2;            // 0..63 tile row for loads
    const int kq = (tid & 3) << 2;      // k sub-offset (0,4,8,12)
    const int ty = tid >> 4, tx = tid & 15;

    unsigned long long acc[4][2];
#pragma unroll
    for (int r = 0; r < 4; r++) { acc[r][0] = 0ull; acc[r][1] = 0ull; }

    for (int k0 = 0; k0 < K; k0 += 16) {
        float4 av = *(const float4*)(A + (size_t)(m0 + lr) * K + k0 + kq);
        float4 bv = *(const float4*)(W + (size_t)(n0 + lr) * K + k0 + kq);
        __syncthreads();
        As[(kq + 0) * 130 + 2 * lr] = av.x; As[(kq + 0) * 130 + 2 * lr + 1] = av.x;
        As[(kq + 1) * 130 + 2 * lr] = av.y; As[(kq + 1) * 130 + 2 * lr + 1] = av.y;
        As[(kq + 2) * 130 + 2 * lr] = av.z; As[(kq + 2) * 130 + 2 * lr + 1] = av.z;
        As[(kq + 3) * 130 + 2 * lr] = av.w; As[(kq + 3) * 130 + 2 * lr + 1] = av.w;
        Bs[(kq + 0) * 66 + lr] = bv.x;
        Bs[(kq + 1) * 66 + lr] = bv.y;
        Bs[(kq + 2) * 66 + lr] = bv.z;
        Bs[(kq + 3) * 66 + lr] = bv.w;
        __syncthreads();
#pragma unroll
        for (int kk = 0; kk < 16; kk++) {
            unsigned long long b01 = *(const unsigned long long*)&Bs[kk * 66 + tx * 4];
            unsigned long long b23 = *(const unsigned long long*)&Bs[kk * 66 + tx * 4 + 2];
#pragma unroll
            for (int r = 0; r < 4; r++) {
                unsigned long long ad =
                    *(const unsigned long long*)&As[kk * 130 + (ty * 4 + r) * 2];
                FMA2(acc[r][0], ad, b01);
                FMA2(acc[r][1], ad, b23);
            }
        }
    }
    const int n = n0 + tx * 4;
    float b0v = bias[n], b1v = bias[n + 1], b2v = bias[n + 2], b3v = bias[n + 3];
#pragma unroll
    for (int r = 0; r < 4; r++) {
        int m = m0 + ty * 4 + r;
        float4 v;
        UNPK2(v.x, v.y, acc[r][0]);
        UNPK2(v.z, v.w, acc[r][1]);
        v.x += b0v; v.y += b1v; v.z += b2v; v.w += b3v;
        if (which == 0) {
            v.x = (v.x > 0.0f) ? expf(-v.x) : 1.0f;
            v.y = (v.y > 0.0f) ? expf(-v.y) : 1.0f;
            v.z = (v.z > 0.0f) ? expf(-v.z) : 1.0f;
            v.w = (v.w > 0.0f) ? expf(-v.w) : 1.0f;
        }
        *(float4*)(C + (size_t)m * N + n) = v;
    }
}

// ---------------- persistent scan kernel ------------------------------------
// One launch, all T=256 steps; atomic-free flag barrier between steps.
// Block: 32 batch rows x 32 h-cols x 6 gates (192 cols), K=512.
// 256 threads = 8 warps = 4 row-groups (8 rows) x 2 k-groups (16 kk each).
// Grid (16,8) = 128 CTAs, all co-resident. Software-pipelined slab loop:
// W/h/gamma for slab s+1 prefetched into registers during compute of slab s.
__global__ void __launch_bounds__(256) scan_kernel(const float* __restrict__ b_hh,
                                                   float* __restrict__ out) {
    __shared__ __align__(16) float Ws[32 * 196];    // [k][c] stride 196 (also S buffer)
    __shared__ __align__(16) float Ad[32 * 66];     // [k][2*row] duplicated
    const int tid = threadIdx.x;
    const int hb = blockIdx.x;          // h-block 0..15
    const int h0 = hb * 32;
    const int b0 = blockIdx.y * 32;
    const int cta = blockIdx.y * 16 + blockIdx.x;

    const int lid = tid & 31;
    const int wid = tid >> 5;
    const int kg  = wid & 1;            // k-group (16 kk each)
    const int rgp = wid >> 1;           // row-group (8 rows each)

    const int ar = tid >> 3;            // h-load row 0..31
    const int akq = (tid & 7) << 2;     // h-load k quarter

    // W smem store mapping (hoisted: f -> row f/48, col (f%48)*4)
    int wsk[6], wsc[6];
#pragma unroll
    for (int i = 0; i < 6; i++) {
        int f = i * 256 + tid;
        wsk[i] = f / 48;
        wsc[i] = (f % 48) * 4;
    }
    const float4* __restrict__ Wt4 = (const float4*)(g_Wt + (size_t)hb * 512 * 192);

    // epilogue mapping + hoisted biases (t-invariant)
    int e_row[4], e_jh[4];
    float bias_r[4], bias_z[4], bias_n[4];
#pragma unroll
    for (int it = 0; it < 4; it++) {
        int item = it * 256 + tid;
        e_row[it] = item >> 5;
        e_jh[it]  = item & 31;
        int gj = h0 + e_jh[it];
        bias_r[it] = b_hh[gj];
        bias_z[it] = b_hh[512 + gj];
        bias_n[it] = b_hh[1024 + gj];
    }

    for (int t = 0; t < T_; t++) {
        const float* __restrict__ hin = g_h[t & 1];
        float* __restrict__ hout = g_h[(t + 1) & 1];
        const float* __restrict__ gbase = g_gamma_h +
            ((size_t)(b0 + ar) * T_ + t) * H_ + akq;
        const float* __restrict__ hbase = hin + (b0 + ar) * H_ + akq;

        unsigned long long acc[8][3];
#pragma unroll
        for (int rr = 0; rr < 8; rr++) {
            acc[rr][0] = 0ull; acc[rr][1] = 0ull; acc[rr][2] = 0ull;
        }

        // prefetch slab 0
        float4 wv[6];
#pragma unroll
        for (int i = 0; i < 6; i++) wv[i] = Wt4[i * 256 + tid];
        float4 hv = *(const float4*)(hbase);
        float4 gv = *(const float4*)(gbase);

        for (int s = 0; s < 16; s++) {
            __syncthreads();
            // store staged regs for slab s
            {
                float a0 = hv.x * gv.x, a1 = hv.y * gv.y;
                float a2 = hv.z * gv.z, a3 = hv.w * gv.w;
                unsigned long long p0, p1, p2, p3;
                DUP2(p0, a0); DUP2(p1, a1); DUP2(p2, a2); DUP2(p3, a3);
                *(unsigned long long*)&Ad[(akq + 0) * 66 + 2 * ar] = p0;
                *(unsigned long long*)&Ad[(akq + 1) * 66 + 2 * ar] = p1;
                *(unsigned long long*)&Ad[(akq + 2) * 66 + 2 * ar] = p2;
                *(unsigned long long*)&Ad[(akq + 3) * 66 + 2 * ar] = p3;
            }
#pragma unroll
            for (int i = 0; i < 6; i++)
                *(float4*)&Ws[wsk[i] * 196 + wsc[i]] = wv[i];
            __syncthreads();
            // prefetch slab s+1 (overlaps with compute below)
            if (s < 15) {
                int base = 1536 * (s + 1);
#pragma unroll
                for (int i = 0; i < 6; i++) wv[i] = Wt4[base + i * 256 + tid];
                hv = *(const float4*)(hbase + (s + 1) * 32);
                gv = *(const float4*)(gbase + (s + 1) * 32);
            }
            // compute slab s
#pragma unroll
            for (int kx = 0; kx < 16; kx++) {
                const int kk = kg * 16 + kx;
                unsigned long long bp0 = *(const unsigned long long*)&Ws[kk * 196 + 2 * lid];
                unsigned long long bp1 = *(const unsigned long long*)&Ws[kk * 196 + 2 * lid + 64];
                unsigned long long bp2 = *(const unsigned long long*)&Ws[kk * 196 + 2 * lid + 128];
#pragma unroll
                for (int rr = 0; rr < 8; rr++) {
                    unsigned long long ad =
                        *(const unsigned long long*)&Ad[kk * 66 + (rgp * 8 + rr) * 2];
                    FMA2(acc[rr][0], ad, bp0);
                    FMA2(acc[rr][1], ad, bp1);
                    FMA2(acc[rr][2], ad, bp2);
                }
            }
        }

        // staged k-group reduction: 2 rounds, reusing Ws as S[row][c] (stride 196)
        float u[4][6];
#pragma unroll
        for (int it = 0; it < 4; it++)
#pragma unroll
            for (int g = 0; g < 6; g++) u[it][g] = 0.0f;

        for (int round = 0; round < 2; round++) {
            __syncthreads();
            if (kg == round) {
#pragma unroll
                for (int rr = 0; rr < 8; rr++) {
#pragma unroll
                    for (int j = 0; j < 3; j++) {
                        *(unsigned long long*)&Ws[(rgp * 8 + rr) * 196 + 2 * lid + 64 * j] =
                            acc[rr][j];
                    }
                }
            }
            __syncthreads();
#pragma unroll
            for (int it = 0; it < 4; it++) {
#pragma unroll
                for (int g = 0; g < 6; g++)
                    u[it][g] += Ws[e_row[it] * 196 + g * 32 + e_jh[it]];
            }
        }

        // gate nonlinearity + state update: 32x32 items, 4 per thread
#pragma unroll
        for (int it = 0; it < 4; it++) {
            int gb = b0 + e_row[it], gj = h0 + e_jh[it];
            size_t ridx = (size_t)gb * T_ + t;
            const float* gi = g_gi + ridx * 1536 + gj;
            float ir  = gi[0]    + u[it][0];
            float iz  = gi[512]  + u[it][1];
            float in_ = gi[1024] + u[it][2];
            float hr_ = u[it][3] + bias_r[it];
            float hz  = u[it][4] + bias_z[it];
            float hn  = u[it][5] + bias_n[it];
            float hd = hin[gb * H_ + gj] * g_gamma_h[ridx * H_ + gj];
            float r = 1.0f / (1.0f + expf(-(ir + hr_)));
            float z = 1.0f / (1.0f + expf(-(iz + hz)));
            float n = tanhf(in_ + r * hn);
            float hvn = (1.0f - z) * n + z * hd;
            hout[gb * H_ + gj] = hvn;
            out[ridx * H_ + gj] = hvn;
            if (t == T_ - 1) out[(size_t)BT * H_ + (size_t)gb * H_ + gj] = hvn;
        }

        // ---- atomic-free grid barrier (flag store + parallel poll) ----
        if (t < T_ - 1) {
            __syncthreads();
            if (tid == 0) {
                __threadfence();
                ((volatile int*)g_flags)[cta] = t + 1;
            }
            if (cta == 0) {
                if (tid < NCTA) {
                    while (((volatile int*)g_flags)[tid] <= t) { }
                    __threadfence();
                }
            } else {
                if (tid == 0) {
                    while (*((volatile int*)&g_gen) <= t) { }
                    __threadfence();
                }
            }
            __syncthreads();
            if (cta == 0 && tid == 0) {
                *((volatile int*)&g_gen) = t + 1;
            }
        }
    }
}

// ---------------- launch ----------------------------------------------------
// Pure kernel launches only; 7 graph nodes total.
extern "C" void kernel_launch(void* const* d_in, const int* in_sizes, int n_in,
                              void* d_out, int out_size) {
    const float* values = (const float*)d_in[0];
    const float* masks  = (const float*)d_in[1];
    const float* deltas = (const float*)d_in[2];
    const float* emean  = (const float*)d_in[3];
    const float* xlocf  = (const float*)d_in[4];
    const float* wx     = (const float*)d_in[5];
    const float* bx     = (const float*)d_in[6];
    const float* Wh     = (const float*)d_in[7];
    const float* bh     = (const float*)d_in[8];
    const float* W_ih   = (const float*)d_in[9];
    const float* W_hh   = (const float*)d_in[10];
    const float* b_ih   = (const float*)d_in[11];
    const float* b_hh   = (const float*)d_in[12];
    float* out = (float*)d_out;

    pack_w2_kernel<<<(1536 * 256) / 256, 256>>>(W_ih);
    pack_wt_kernel<<<(16 * 512 * 192) / 256, 256>>>(W_ih, W_hh);
    xm_kernel<<<(BT * F_) / 256, 256>>>(values, masks, deltas, emean, xlocf, wx, bx);
    zero_h_kernel<<<(B_ * H_) / 256, 256>>>();
    // gamma_h = exp(-relu(deltas @ Wh^T + bh)) : [BT,128] x [512,128]^T
    gemm_f2_kernel<<<dim3(512 / 64, BT / 64), 256>>>(deltas, Wh, bh, 0);
    // gi_pre = xm @ W2^T + b_ih : [BT,256] x [1536,256]^T (A/W resolved in-kernel)
    gemm_f2_kernel<<<dim3(1536 / 64, BT / 64), 256>>>(nullptr, nullptr, b_ih, 1);
    // persistent scan over all timesteps
    scan_kernel<<<dim3(16, 8), 256>>>(b_hh, out);
}